// round 8
// baseline (speedup 1.0000x reference)
#include <cuda_runtime.h>
#include <cstdint>
#include <cstddef>

#define T_STEPS 2048
#define HID     128
#define BATCH   256

typedef unsigned long long ull;

// folded FC: M[128][3] then c[3]
__device__ float g_fold[128 * 3 + 4];

// ---- packed f32x2 helpers (sm_100+ PTX) ----
__device__ __forceinline__ ull fma2(ull a, ull b, ull c) {
    ull d;
    asm("fma.rn.f32x2 %0, %1, %2, %3;" : "=l"(d) : "l"(a), "l"(b), "l"(c));
    return d;
}
__device__ __forceinline__ ull add2(ull a, ull b) {
    ull d;
    asm("add.rn.f32x2 %0, %1, %2;" : "=l"(d) : "l"(a), "l"(b));
    return d;
}
__device__ __forceinline__ void unpack2(ull u, float& x, float& y) {
    asm("mov.b64 {%0, %1}, %2;" : "=f"(x), "=f"(y) : "l"(u));
}

// tanh(|x|) = (1 - e)/(1 + e), e = exp(-2|x|) via MUFU EX2 (~2 ulp)
__device__ __forceinline__ float fast_tanh(float x) {
    float ax = fabsf(x);
    float e  = __expf(-2.0f * ax);
    float r  = __fdividef(1.0f - e, 1.0f + e);
    return copysignf(r, x);
}

// ---- tiny kernel: fold the two FC layers into a 128->3 affine map ----
__global__ void fold_kernel(const float* __restrict__ W_fc1,
                            const float* __restrict__ b_fc1,
                            const float* __restrict__ W_fc2,
                            const float* __restrict__ b_fc2) {
    int h = threadIdx.x;  // 0..127
    float m0 = 0.f, m1 = 0.f, m2 = 0.f;
    #pragma unroll 8
    for (int f = 0; f < 64; f++) {
        float w = W_fc1[f * 128 + h];
        m0 = fmaf(w, W_fc2[0 * 64 + f], m0);
        m1 = fmaf(w, W_fc2[1 * 64 + f], m1);
        m2 = fmaf(w, W_fc2[2 * 64 + f], m2);
    }
    g_fold[h * 3 + 0] = m0;
    g_fold[h * 3 + 1] = m1;
    g_fold[h * 3 + 2] = m2;
    if (h < 3) {
        float c = b_fc2[h];
        for (int f = 0; f < 64; f++) c = fmaf(b_fc1[f], W_fc2[h * 64 + f], c);
        g_fold[384 + h] = c;
    }
}

// shared layout (floats):
//   x_sh  : 2*2048*3        = 12288   @ 0
//   h_sh  : 2(parity)*2*128 = 512     @ 12288   (ping-pong)
//   ring  : 2(half)*2*64*129= 33024   @ 12800   (double-buffered, pitch 129)
//   Msh   : 384                       @ 45824
//   csh   : 4                         @ 46208
#define OFF_H    12288
#define OFF_RING 12800
#define OFF_M    45824
#define OFF_C    46208
#define SMEM_FLOATS 46212
#define SMEM_BYTES  (SMEM_FLOATS * 4)
#define RING_HALF   (2 * 64 * 129)   // 16512

__global__ __launch_bounds__(256, 1)
void rnn_kernel(const float* __restrict__ x,
                const float* __restrict__ hidden,
                const float* __restrict__ W_ih,
                const float* __restrict__ W_hh,
                const float* __restrict__ b_ih,
                const float* __restrict__ b_hh,
                float* __restrict__ out) {
    extern __shared__ float sm[];
    float* x_sh = sm;
    float* h_sh = sm + OFF_H;      // [parity][row][128]
    float* ring = sm + OFF_RING;   // [half][row][64][129]
    float* Msh  = sm + OFF_M;      // [128][3]
    float* csh  = sm + OFF_C;      // [3]

    const int tid = threadIdx.x;
    const int lr  = tid >> 7;        // local row (0/1)
    const int j   = tid & 127;       // hidden index this thread owns
    const int r0  = blockIdx.x * 2;  // first of 2 batch rows

    // stage x for both rows (rows are contiguous in gmem)
    const float* xg = x + (size_t)r0 * (T_STEPS * 3);
    for (int idx = tid; idx < 2 * T_STEPS * 3; idx += 256) x_sh[idx] = xg[idx];

    // stage folded FC map
    for (int idx = tid; idx < 384; idx += 256) Msh[idx] = g_fold[idx];
    if (tid < 3) csh[tid] = g_fold[384 + tid];

    // initial hidden state -> parity-0 buffer
    h_sh[lr * 128 + j] = hidden[(size_t)(r0 + lr) * HID + j];

    // W_hh row j resident in registers as 64 packed f32x2
    ull w[64];
    const ull* wrow = (const ull*)(W_hh + j * HID);
    #pragma unroll
    for (int i = 0; i < 64; i++) w[i] = wrow[i];

    const float wi0 = W_ih[j * 3 + 0];
    const float wi1 = W_ih[j * 3 + 1];
    const float wi2 = W_ih[j * 3 + 2];
    const float bc  = b_ih[j] + b_hh[j];

    const float* xrow = x_sh + lr * (T_STEPS * 3);

    __syncthreads();

    for (int t = 0; t < T_STEPS; t++) {
        const int p    = t & 1;
        const int tl   = t & 63;
        const int half = (t >> 6) & 1;

        // input projection (x has only 3 features; broadcast LDS)
        float x0 = xrow[t * 3 + 0], x1 = xrow[t * 3 + 1], x2 = xrow[t * 3 + 2];
        float s = fmaf(wi2, x2, fmaf(wi1, x1, fmaf(wi0, x0, bc)));

        // h . W_hh[j] for my row: 64 packed f32x2 FMAs, 4 chains
        ull a0 = 0, a1 = 0, a2 = 0, a3 = 0;
        const ulonglong2* hv = (const ulonglong2*)(h_sh + p * 256 + lr * 128);
        #pragma unroll
        for (int i = 0; i < 32; i++) {
            ulonglong2 v = hv[i];
            if (i & 1) {
                a2 = fma2(v.x, w[2 * i], a2);
                a3 = fma2(v.y, w[2 * i + 1], a3);
            } else {
                a0 = fma2(v.x, w[2 * i], a0);
                a1 = fma2(v.y, w[2 * i + 1], a1);
            }
        }
        ull ra = add2(add2(a0, a2), add2(a1, a3));
        float f0, f1;
        unpack2(ra, f0, f1);
        float hn = fast_tanh(s + (f0 + f1));

        // write to the OTHER parity buffer + current ring half (no pre-barrier needed)
        h_sh[(p ^ 1) * 256 + lr * 128 + j] = hn;
        ring[half * RING_HALF + lr * (64 * 129) + tl * 129 + j] = hn;
        __syncthreads();   // new h + ring visible for next step / FC

        // every 64 steps: folded FC for the 128 (row,t) pairs in this ring half.
        // Runs after the barrier; overlaps with the other warps' next-step work.
        // The next cycle writes the other ring half -> no overwrite race.
        if (tl == 63 && tid < 128) {
            int rr  = tid >> 6;        // which row
            int ttl = tid & 63;        // which timestep in ring
            const float* hr = ring + half * RING_HALF + rr * (64 * 129) + ttl * 129;
            float o0 = csh[0], o1 = csh[1], o2 = csh[2];
            #pragma unroll 16
            for (int k = 0; k < 128; k++) {
                float hvv = hr[k];
                o0 = fmaf(hvv, Msh[3 * k + 0], o0);
                o1 = fmaf(hvv, Msh[3 * k + 1], o1);
                o2 = fmaf(hvv, Msh[3 * k + 2], o2);
            }
            int tg = t - 63 + ttl;
            float* op = out + ((size_t)(r0 + rr) * T_STEPS + tg) * 3;
            op[0] = o0; op[1] = o1; op[2] = o2;
        }
    }

    // final hidden state (T even -> lives in parity-0 buffer)
    float* hT = out + (size_t)BATCH * T_STEPS * 3;
    hT[(size_t)(r0 + lr) * HID + j] = h_sh[lr * 128 + j];
}

extern "C" void kernel_launch(void* const* d_in, const int* in_sizes, int n_in,
                              void* d_out, int out_size) {
    const float* x      = (const float*)d_in[0];
    const float* hidden = (const float*)d_in[1];
    const float* W_ih   = (const float*)d_in[2];
    const float* W_hh   = (const float*)d_in[3];
    const float* b_ih   = (const float*)d_in[4];
    const float* b_hh   = (const float*)d_in[5];
    const float* W_fc1  = (const float*)d_in[6];
    const float* b_fc1  = (const float*)d_in[7];
    const float* W_fc2  = (const float*)d_in[8];
    const float* b_fc2  = (const float*)d_in[9];
    float* out = (float*)d_out;

    cudaFuncSetAttribute(rnn_kernel, cudaFuncAttributeMaxDynamicSharedMemorySize, SMEM_BYTES);

    fold_kernel<<<1, 128>>>(W_fc1, b_fc1, W_fc2, b_fc2);
    rnn_kernel<<<BATCH / 2, 256, SMEM_BYTES>>>(x, hidden, W_ih, W_hh, b_ih, b_hh, out);
}

// round 11
// speedup vs baseline: 1.0196x; 1.0196x over previous
#include <cuda_runtime.h>
#include <cstdint>
#include <cstddef>

#define T_STEPS 2048
#define HID     128
#define BATCH   256

typedef unsigned long long ull;

// folded FC: M[128][3] then c[3]
__device__ float g_fold[128 * 3 + 4];

// ---- packed f32x2 helpers (sm_100+ PTX) ----
__device__ __forceinline__ ull fma2(ull a, ull b, ull c) {
    ull d;
    asm("fma.rn.f32x2 %0, %1, %2, %3;" : "=l"(d) : "l"(a), "l"(b), "l"(c));
    return d;
}
__device__ __forceinline__ ull add2(ull a, ull b) {
    ull d;
    asm("add.rn.f32x2 %0, %1, %2;" : "=l"(d) : "l"(a), "l"(b));
    return d;
}
__device__ __forceinline__ void unpack2(ull u, float& x, float& y) {
    asm("mov.b64 {%0, %1}, %2;" : "=f"(x), "=f"(y) : "l"(u));
}

// tanh(|x|) = (1 - e)/(1 + e), e = exp(-2|x|) via MUFU EX2 (~2 ulp)
__device__ __forceinline__ float fast_tanh(float x) {
    float ax = fabsf(x);
    float e  = __expf(-2.0f * ax);
    float r  = __fdividef(1.0f - e, 1.0f + e);
    return copysignf(r, x);
}

// ---- tiny kernel: fold the two FC layers into a 128->3 affine map ----
__global__ void fold_kernel(const float* __restrict__ W_fc1,
                            const float* __restrict__ b_fc1,
                            const float* __restrict__ W_fc2,
                            const float* __restrict__ b_fc2) {
    int h = threadIdx.x;  // 0..127
    float m0 = 0.f, m1 = 0.f, m2 = 0.f;
    #pragma unroll 8
    for (int f = 0; f < 64; f++) {
        float w = W_fc1[f * 128 + h];
        m0 = fmaf(w, W_fc2[0 * 64 + f], m0);
        m1 = fmaf(w, W_fc2[1 * 64 + f], m1);
        m2 = fmaf(w, W_fc2[2 * 64 + f], m2);
    }
    g_fold[h * 3 + 0] = m0;
    g_fold[h * 3 + 1] = m1;
    g_fold[h * 3 + 2] = m2;
    if (h < 3) {
        float c = b_fc2[h];
        for (int f = 0; f < 64; f++) c = fmaf(b_fc1[f], W_fc2[h * 64 + f], c);
        g_fold[384 + h] = c;
    }
}

// shared layout (floats), ONE batch row per CTA:
//   x_sh  : 2048*3          = 6144    @ 0
//   h_sh  : 2(parity)*128   = 256     @ 6144   (ping-pong)
//   ring  : 2(half)*64*129  = 16512   @ 6400   (double-buffered, pitch 129)
//   Msh   : 384                       @ 22912
//   csh   : 4                         @ 23296
// total 23300 floats = 93200 B  -> 2 CTAs/SM co-resident (186KB < 227KB)
#define OFF_H    6144
#define OFF_RING 6400
#define OFF_M    22912
#define OFF_C    23296
#define SMEM_FLOATS 23300
#define SMEM_BYTES  (SMEM_FLOATS * 4)
#define RING_HALF   (64 * 129)   // 8256

__global__ __launch_bounds__(128, 2)
void rnn_kernel(const float* __restrict__ x,
                const float* __restrict__ hidden,
                const float* __restrict__ W_ih,
                const float* __restrict__ W_hh,
                const float* __restrict__ b_ih,
                const float* __restrict__ b_hh,
                float* __restrict__ out) {
    extern __shared__ float sm[];
    float* x_sh = sm;
    float* h_sh = sm + OFF_H;      // [parity][128]
    float* ring = sm + OFF_RING;   // [half][64][129]
    float* Msh  = sm + OFF_M;      // [128][3]
    float* csh  = sm + OFF_C;      // [3]

    const int j = threadIdx.x;     // hidden index this thread owns
    const int r = blockIdx.x;      // batch row this CTA owns

    // stage x for this row
    const float* xg = x + (size_t)r * (T_STEPS * 3);
    for (int idx = j; idx < T_STEPS * 3; idx += 128) x_sh[idx] = xg[idx];

    // stage folded FC map
    for (int idx = j; idx < 384; idx += 128) Msh[idx] = g_fold[idx];
    if (j < 3) csh[j] = g_fold[384 + j];

    // initial hidden state -> parity-0 buffer
    h_sh[j] = hidden[(size_t)r * HID + j];

    // W_hh row j resident in registers as 64 packed f32x2
    ull w[64];
    const ull* wrow = (const ull*)(W_hh + j * HID);
    #pragma unroll
    for (int i = 0; i < 64; i++) w[i] = wrow[i];

    const float wi0 = W_ih[j * 3 + 0];
    const float wi1 = W_ih[j * 3 + 1];
    const float wi2 = W_ih[j * 3 + 2];
    const float bc  = b_ih[j] + b_hh[j];

    __syncthreads();

    for (int t = 0; t < T_STEPS; t++) {
        const int p    = t & 1;
        const int tl   = t & 63;
        const int half = (t >> 6) & 1;

        // input projection (x has only 3 features; broadcast LDS)
        float x0 = x_sh[t * 3 + 0], x1 = x_sh[t * 3 + 1], x2 = x_sh[t * 3 + 2];
        float s = fmaf(wi2, x2, fmaf(wi1, x1, fmaf(wi0, x0, bc)));

        // h . W_hh[j]: 64 packed f32x2 FMAs, 4 independent chains
        ull a0 = 0, a1 = 0, a2 = 0, a3 = 0;
        const ulonglong2* hv = (const ulonglong2*)(h_sh + p * 128);
        #pragma unroll
        for (int i = 0; i < 32; i++) {
            ulonglong2 v = hv[i];
            if (i & 1) {
                a2 = fma2(v.x, w[2 * i], a2);
                a3 = fma2(v.y, w[2 * i + 1], a3);
            } else {
                a0 = fma2(v.x, w[2 * i], a0);
                a1 = fma2(v.y, w[2 * i + 1], a1);
            }
        }
        ull ra = add2(add2(a0, a2), add2(a1, a3));
        float f0, f1;
        unpack2(ra, f0, f1);
        float hn = fast_tanh(s + (f0 + f1));

        // write to the OTHER parity buffer + current ring half
        h_sh[(p ^ 1) * 128 + j] = hn;
        ring[half * RING_HALF + tl * 129 + j] = hn;
        __syncthreads();   // ONE barrier per step: new h + ring visible

        // every 64 steps: folded FC for the 64 timesteps in this ring half.
        // 2 warps do it; the other 2 run ahead into the next step. The next
        // 64 steps write the other half -> no overwrite race.
        if (tl == 63 && j < 64) {
            const float* hr = ring + half * RING_HALF + j * 129;
            float o0 = csh[0], o1 = csh[1], o2 = csh[2];
            #pragma unroll 16
            for (int k = 0; k < 128; k++) {
                float hvv = hr[k];
                o0 = fmaf(hvv, Msh[3 * k + 0], o0);
                o1 = fmaf(hvv, Msh[3 * k + 1], o1);
                o2 = fmaf(hvv, Msh[3 * k + 2], o2);
            }
            int tg = t - 63 + j;
            float* op = out + ((size_t)r * T_STEPS + tg) * 3;
            op[0] = o0; op[1] = o1; op[2] = o2;
        }
    }

    // final hidden state (T even -> lives in parity-0 buffer)
    float* hT = out + (size_t)BATCH * T_STEPS * 3;
    hT[(size_t)r * HID + j] = h_sh[j];
}

extern "C" void kernel_launch(void* const* d_in, const int* in_sizes, int n_in,
                              void* d_out, int out_size) {
    const float* x      = (const float*)d_in[0];
    const float* hidden = (const float*)d_in[1];
    const float* W_ih   = (const float*)d_in[2];
    const float* W_hh   = (const float*)d_in[3];
    const float* b_ih   = (const float*)d_in[4];
    const float* b_hh   = (const float*)d_in[5];
    const float* W_fc1  = (const float*)d_in[6];
    const float* b_fc1  = (const float*)d_in[7];
    const float* W_fc2  = (const float*)d_in[8];
    const float* b_fc2  = (const float*)d_in[9];
    float* out = (float*)d_out;

    cudaFuncSetAttribute(rnn_kernel, cudaFuncAttributeMaxDynamicSharedMemorySize, SMEM_BYTES);

    fold_kernel<<<1, 128>>>(W_fc1, b_fc1, W_fc2, b_fc2);
    rnn_kernel<<<BATCH, 128, SMEM_BYTES>>>(x, hidden, W_ih, W_hh, b_ih, b_hh, out);
}

// round 12
// speedup vs baseline: 1.1446x; 1.1225x over previous
#include <cuda_runtime.h>
#include <cstdint>
#include <cstddef>

#define T_STEPS 2048
#define HID     128
#define BATCH   256

typedef unsigned long long ull;

// folded FC, transposed planes: M0[128], M1[128], M2[128], c[3]
__device__ __align__(16) float g_fold[3 * 128 + 4];

// ---- packed f32x2 helpers ----
__device__ __forceinline__ ull fma2(ull a, ull b, ull c) {
    ull d;
    asm("fma.rn.f32x2 %0, %1, %2, %3;" : "=l"(d) : "l"(a), "l"(b), "l"(c));
    return d;
}
__device__ __forceinline__ ull add2(ull a, ull b) {
    ull d;
    asm("add.rn.f32x2 %0, %1, %2;" : "=l"(d) : "l"(a), "l"(b));
    return d;
}
__device__ __forceinline__ void unpack2(ull u, float& x, float& y) {
    asm("mov.b64 {%0, %1}, %2;" : "=f"(x), "=f"(y) : "l"(u));
}

// tanh via MUFU: tanh(|x|) = (1-e)/(1+e), e = exp(-2|x|)
__device__ __forceinline__ float fast_tanh(float x) {
    float ax = fabsf(x);
    float e  = __expf(-2.0f * ax);
    float r  = __fdividef(1.0f - e, 1.0f + e);
    return copysignf(r, x);
}

__global__ void fold_kernel(const float* __restrict__ W_fc1,
                            const float* __restrict__ b_fc1,
                            const float* __restrict__ W_fc2,
                            const float* __restrict__ b_fc2) {
    int h = threadIdx.x;  // 0..127
    float m0 = 0.f, m1 = 0.f, m2 = 0.f;
    #pragma unroll 8
    for (int f = 0; f < 64; f++) {
        float w = W_fc1[f * 128 + h];
        m0 = fmaf(w, W_fc2[0 * 64 + f], m0);
        m1 = fmaf(w, W_fc2[1 * 64 + f], m1);
        m2 = fmaf(w, W_fc2[2 * 64 + f], m2);
    }
    g_fold[0 * 128 + h] = m0;
    g_fold[1 * 128 + h] = m1;
    g_fold[2 * 128 + h] = m2;
    if (h < 3) {
        float c = b_fc2[h];
        for (int f = 0; f < 64; f++) c = fmaf(b_fc1[f], W_fc2[h * 64 + f], c);
        g_fold[384 + h] = c;
    }
}

// shared layout (floats):
//   x4   : 2*2048*4      = 16384 @ 0       (x padded to float4 -> 1 LDS.128/row/step)
//   h    : 2(par)*2*128  = 512   @ 16384
//   ring : 2(half)*2*64*130 = 33280 @ 16896  (pitch 130: 8B-aligned LDS.64 reads)
//   M    : 384           @ 50176  (M0|M1|M2 planes)
//   c    : 4             @ 50560
#define OFF_H     16384
#define OFF_RING  16896
#define RING_ROW  (64 * 130)      // 8320
#define RING_HALF (2 * RING_ROW)  // 16640
#define OFF_M     50176
#define OFF_C     50560
#define SMEM_FLOATS 50564
#define SMEM_BYTES  (SMEM_FLOATS * 4)

__global__ __launch_bounds__(128, 1)
void rnn_kernel(const float* __restrict__ x,
                const float* __restrict__ hidden,
                const float* __restrict__ W_ih,
                const float* __restrict__ W_hh,
                const float* __restrict__ b_ih,
                const float* __restrict__ b_hh,
                float* __restrict__ out) {
    extern __shared__ float sm[];
    float4* x4v  = (float4*)sm;          // [2][2048]
    float*  h_sh = sm + OFF_H;           // [parity][row][128]
    float*  ring = sm + OFF_RING;        // [half][row][64][130]
    float*  Msh  = sm + OFF_M;           // [3][128]
    float*  csh  = sm + OFF_C;           // [3]

    const int j  = threadIdx.x;
    const int r0 = blockIdx.x * 2;

    // stage x, padded to float4
    for (int base = j; base < 2 * T_STEPS; base += 128) {
        int row = base >> 11, t = base & 2047;
        const float* p = x + ((size_t)(r0 + row) * T_STEPS + t) * 3;
        x4v[row * T_STEPS + t] = make_float4(p[0], p[1], p[2], 0.f);
    }
    for (int idx = j; idx < 384; idx += 128) Msh[idx] = g_fold[idx];
    if (j < 3) csh[j] = g_fold[384 + j];

    h_sh[j]       = hidden[(size_t)r0 * HID + j];
    h_sh[128 + j] = hidden[(size_t)(r0 + 1) * HID + j];

    // W_hh row j in registers (64 packed f32x2)
    ull w[64];
    const ull* wrow = (const ull*)(W_hh + j * HID);
    #pragma unroll
    for (int i = 0; i < 64; i++) w[i] = wrow[i];

    const float wi0 = W_ih[j * 3 + 0];
    const float wi1 = W_ih[j * 3 + 1];
    const float wi2 = W_ih[j * 3 + 2];
    const float bc  = b_ih[j] + b_hh[j];

    // smeared-FC state: this thread owns output pair (row rr, local time t0)
    const int rr = j >> 6, t0 = j & 63;
    ull oa0 = 0, oa1 = 0, oa2 = 0;
    const float* fcbase = ring + rr * RING_ROW + t0 * 130;

    __syncthreads();

    // one RNN step; doFC consumes 2 ring entries of the opposite half
    auto step = [&](int t, int tl, int p, int wh, bool doFC) {
        float4 xa = x4v[t];
        float4 xb = x4v[T_STEPS + t];
        float s0 = fmaf(wi2, xa.z, fmaf(wi1, xa.y, fmaf(wi0, xa.x, bc)));
        float s1 = fmaf(wi2, xb.z, fmaf(wi1, xb.y, fmaf(wi0, xb.x, bc)));

        if (doFC) {  // independent of h -> fills stall shadows
            int k2 = tl * 2;
            ull rp = *(const ull*)(fcbase + (wh ^ 1) * RING_HALF + k2);
            oa0 = fma2(rp, *(const ull*)(Msh + k2),       oa0);
            oa1 = fma2(rp, *(const ull*)(Msh + 128 + k2), oa1);
            oa2 = fma2(rp, *(const ull*)(Msh + 256 + k2), oa2);
        }

        ull a0 = 0, a1 = 0, a2 = 0, a3 = 0;
        ull b0 = 0, b1 = 0, b2 = 0, b3 = 0;
        const ulonglong2* hA = (const ulonglong2*)(h_sh + p * 256);
        const ulonglong2* hB = (const ulonglong2*)(h_sh + p * 256 + 128);
        #pragma unroll
        for (int i = 0; i < 32; i++) {
            ulonglong2 va = hA[i], vb = hB[i];
            if (i & 1) {
                a2 = fma2(va.x, w[2 * i], a2); a3 = fma2(va.y, w[2 * i + 1], a3);
                b2 = fma2(vb.x, w[2 * i], b2); b3 = fma2(vb.y, w[2 * i + 1], b3);
            } else {
                a0 = fma2(va.x, w[2 * i], a0); a1 = fma2(va.y, w[2 * i + 1], a1);
                b0 = fma2(vb.x, w[2 * i], b0); b1 = fma2(vb.y, w[2 * i + 1], b1);
            }
        }
        ull ra = add2(add2(a0, a2), add2(a1, a3));
        ull rb = add2(add2(b0, b2), add2(b1, b3));
        float fa0, fa1, fb0, fb1;
        unpack2(ra, fa0, fa1);
        unpack2(rb, fb0, fb1);
        float h0 = fast_tanh(s0 + (fa0 + fa1));
        float h1 = fast_tanh(s1 + (fb0 + fb1));

        h_sh[(p ^ 1) * 256 + j]       = h0;
        h_sh[(p ^ 1) * 256 + 128 + j] = h1;
        float* rg = ring + wh * RING_HALF + tl * 130;
        rg[j] = h0;
        rg[RING_ROW + j] = h1;
        __syncthreads();
    };

    // window 0: no FC consumption yet
    #pragma unroll 2
    for (int tl = 0; tl < 64; tl++) step(tl, tl, tl & 1, 0, false);

    // windows 1..31: smear FC of previous window, finalize at window end
    for (int wdw = 1; wdw < 32; wdw++) {
        const int wh = wdw & 1;
        #pragma unroll 2
        for (int tl = 0; tl < 64; tl++) step(wdw * 64 + tl, tl, tl & 1, wh, true);

        float f0a, f0b, f1a, f1b, f2a, f2b;
        unpack2(oa0, f0a, f0b);
        unpack2(oa1, f1a, f1b);
        unpack2(oa2, f2a, f2b);
        int tg = (wdw - 1) * 64 + t0;
        float* op = out + ((size_t)(r0 + rr) * T_STEPS + tg) * 3;
        op[0] = f0a + f0b + csh[0];
        op[1] = f1a + f1b + csh[1];
        op[2] = f2a + f2b + csh[2];
        oa0 = oa1 = oa2 = 0;
    }

    // flush FC for the last window (half 1)
    {
        const float* rp0 = fcbase + RING_HALF;
        #pragma unroll 8
        for (int k2 = 0; k2 < 128; k2 += 2) {
            ull rp = *(const ull*)(rp0 + k2);
            oa0 = fma2(rp, *(const ull*)(Msh + k2),       oa0);
            oa1 = fma2(rp, *(const ull*)(Msh + 128 + k2), oa1);
            oa2 = fma2(rp, *(const ull*)(Msh + 256 + k2), oa2);
        }
        float f0a, f0b, f1a, f1b, f2a, f2b;
        unpack2(oa0, f0a, f0b);
        unpack2(oa1, f1a, f1b);
        unpack2(oa2, f2a, f2b);
        int tg = 31 * 64 + t0;
        float* op = out + ((size_t)(r0 + rr) * T_STEPS + tg) * 3;
        op[0] = f0a + f0b + csh[0];
        op[1] = f1a + f1b + csh[1];
        op[2] = f2a + f2b + csh[2];
    }

    // final hidden state (each window ends with h in parity-0 buffer)
    float* hT = out + (size_t)BATCH * T_STEPS * 3;
    hT[(size_t)r0 * HID + j]       = h_sh[j];
    hT[(size_t)(r0 + 1) * HID + j] = h_sh[128 + j];
}

extern "C" void kernel_launch(void* const* d_in, const int* in_sizes, int n_in,
                              void* d_out, int out_size) {
    const float* x      = (const float*)d_in[0];
    const float* hidden = (const float*)d_in[1];
    const float* W_ih   = (const float*)d_in[2];
    const float* W_hh   = (const float*)d_in[3];
    const float* b_ih   = (const float*)d_in[4];
    const float* b_hh   = (const float*)d_in[5];
    const float* W_fc1  = (const float*)d_in[6];
    const float* b_fc1  = (const float*)d_in[7];
    const float* W_fc2  = (const float*)d_in[8];
    const float* b_fc2  = (const float*)d_in[9];
    float* out = (float*)d_out;

    cudaFuncSetAttribute(rnn_kernel, cudaFuncAttributeMaxDynamicSharedMemorySize, SMEM_BYTES);

    fold_kernel<<<1, 128>>>(W_fc1, b_fc1, W_fc2, b_fc2);
    rnn_kernel<<<BATCH / 2, 128, SMEM_BYTES>>>(x, hidden, W_ih, W_hh, b_ih, b_hh, out);
}